// round 13
// baseline (speedup 1.0000x reference)
#include <cuda_runtime.h>
#include <cuda_fp16.h>
#include <cstdint>
#include <cstddef>

#define N_CAM 6
#define C_CH  128
#define H_IMG 64
#define W_IMG 176
#define HW    (H_IMG * W_IMG)     // 11264
#define NQ    640000              // 200*200*16

// 64-channel x 32-hw transpose tiles: (HW/32) * (C/64) * N_CAM
#define TPC      ((HW / 32) * (C_CH / 64))           // 704 per cam
#define T_BLOCKS (TPC * N_CAM)                       // 4224
#define I_BLOCKS (NQ / 1024)                         // 625 (4 q/thread)
#define P_BLOCKS (T_BLOCKS + I_BLOCKS)               // 4849
#define I_SPAN   (7 * I_BLOCKS)                      // 4375 (bid%7==6 -> index)

#define N_TILES  (NQ / 64)                           // 10000 gather tiles
#define G_GRID   (148 * 8)                           // 1184 persistent blocks

// Scratch: img_feats transposed to (cam, h, w, c), fp16 (rn; measured
// whole-output rel_err 2.1e-4 << 1e-3). 17.3 MB static __device__.
__device__ __half g_scratch_h[(size_t)N_CAM * HW * C_CH];
// Per-query packed spatial index into scratch (row index), -1 invalid.
__device__ int g_idx[NQ];

// ---- cache-hinted accessors (createpolicy + L2::cache_hint) ----------------
__device__ __forceinline__ unsigned long long policy_evict_last() {
    unsigned long long p;
    asm("createpolicy.fractional.L2::evict_last.b64 %0, 1.0;" : "=l"(p));
    return p;
}
__device__ __forceinline__ void stg_el_u32(unsigned int* ptr, unsigned int v,
                                           unsigned long long pol) {
    asm volatile("st.global.L2::cache_hint.b32 [%0], %1, %2;"
                 :: "l"(ptr), "r"(v), "l"(pol));
}

// ---------------------------------------------------------------------------
// Fused prologue, role-interleaved (every 7th block -> index role). R12 form:
// Role A: 64c x 32hw transpose tile, f32->fp16, half2-packed 128B store
//   wavefronts; scratch writes pinned in L2 (evict_last).
// Role B: index precompute, 4 queries/thread (uint/uint4 valid loads, 4
//   independent cam-selects + pts loads, one int4 g_idx store).
// Valid dtype detected per block: 1-byte bool has ~30% nonzero bytes at
// offsets ≡ 1 (mod 4); int32/f32 encodings of 0/1 have 0x00 there.
// 1024 samples -> P(false negative) ~ 0.7^1024.
// ---------------------------------------------------------------------------
__global__ __launch_bounds__(256) void prologue_kernel(
    const float* __restrict__ img,
    const float* __restrict__ pts,
    const void*  __restrict__ valid)
{
    const int tid = threadIdx.x;
    const int bid = blockIdx.x;
    const bool is_index = (bid < I_SPAN) && (bid % 7 == 6);

    if (!is_index) {
        // ---- transpose role: 64 channels x 32 hw positions ----
        const int t_id = (bid < I_SPAN) ? (bid - (bid + 1) / 7)
                                        : (bid - I_BLOCKS);
        __shared__ float tile[64][33];
        int b = t_id;
        const int cam = b / TPC;
        b -= cam * TPC;
        const int cb  = b / (HW / 32);               // 0..1
        const int hwb = b - cb * (HW / 32);
        const int hw0 = hwb * 32;
        const int c0  = cb * 64;
        const int tx = tid & 31, ty = tid >> 5;      // 32 x 8

        const unsigned long long pol = policy_evict_last();
        const float* src = img + (size_t)cam * C_CH * HW;
        __half*      dst = g_scratch_h + (size_t)cam * HW * C_CH;

#pragma unroll
        for (int k = 0; k < 8; k++) {
            int c = ty + k * 8;                      // 0..63 within tile
            tile[c][tx] = __ldcs(&src[(size_t)(c0 + c) * HW + hw0 + tx]);
        }
        __syncthreads();
#pragma unroll
        for (int i = 0; i < 4; i++) {
            const int r = ty * 4 + i;                // hw row 0..31
            __half2 h = __floats2half2_rn(tile[2 * tx][r], tile[2 * tx + 1][r]);
            unsigned int* p = (unsigned int*)
                (dst + (size_t)(hw0 + r) * C_CH + c0) + tx;
            stg_el_u32(p, *(unsigned int*)&h, pol);
        }
    } else {
        // ---- index role: 4 queries per thread ----
        const int q4 = (bid / 7) * 1024 + tid * 4;
        const unsigned char* vb = (const unsigned char*)valid;

        int found = 0;
#pragma unroll
        for (int j = 0; j < 4; j++)
            if (vb[1 + 4 * (tid * 4 + j)] != 0) found = 1;
        const int isByte = __syncthreads_or(found);

        unsigned int vmask[N_CAM];
        if (isByte) {
#pragma unroll
            for (int cc = 0; cc < N_CAM; cc++)
                vmask[cc] = *(const unsigned int*)(vb + (size_t)cc * NQ + q4);
        } else {
            const uint4* vw4 = (const uint4*)valid;
#pragma unroll
            for (int cc = 0; cc < N_CAM; cc++) {
                uint4 v = __ldg(&vw4[((size_t)cc * NQ + q4) >> 2]);
                vmask[cc] = (v.x ? 1u : 0u) | (v.y ? 0x100u : 0u) |
                            (v.z ? 0x10000u : 0u) | (v.w ? 0x1000000u : 0u);
            }
        }

        int4 pout;
        int* po = &pout.x;
#pragma unroll
        for (int j = 0; j < 4; j++) {
            int cam = -1;
#pragma unroll
            for (int cc = 0; cc < N_CAM; cc++)
                if ((vmask[cc] >> (8 * j)) & 0xffu) cam = cc;
            int p = -1;
            if (cam >= 0) {
                float2 sp = __ldg(&((const float2*)pts)[(size_t)cam * NQ + q4 + j]);
                int x = min(max(__float2int_rn(sp.x), 0), W_IMG - 1);
                int y = min(max(__float2int_rn(sp.y), 0), H_IMG - 1);
                p = cam * HW + y * W_IMG + x;
            }
            po[j] = p;
        }
        *(int4*)(g_idx + q4) = pout;
    }
}

// ---------------------------------------------------------------------------
// Persistent gather: 1184 blocks grid-stride over 10000 tiles (8-9 each).
// Kills the 0.45-partial-wave tail and amortizes block start; next tile's
// g_idx is prefetched during the current tile's cp.async wait, removing the
// idx-load -> shfl -> cp.async serial chain from the steady-state path.
// Per tile (R11 internals, proven): 64 queries x 128 fp16 channels, 16KB
// smem, per-warp cp.async MLP=8, swizzled 8B layout slot(q,u)=q*32+(u^(q&31)).
// Phase A: cp.async.ca 8B + L2 evict-hint; invalid queries zero-fill (size 0).
// Phase B: LDS.64 -> half2->float2 -> coalesced STG.32 streams (__stcs
// evict-first: the 328MB output stream must not evict the L2 scratch).
// ---------------------------------------------------------------------------
__global__ __launch_bounds__(256) void gather_kernel(float* __restrict__ out)
{
    __shared__ uint2 sm8[64 * 32];      // 16 KB
    const int tid = threadIdx.x;
    const int w = tid >> 5, l = tid & 31;

    const unsigned long long pol = policy_evict_last();
    const char* scr = (const char*)g_scratch_h;
    const unsigned int smem_base =
        (unsigned int)__cvta_generic_to_shared(sm8);

    int pv = 0;
    if (l < 8) pv = g_idx[blockIdx.x * 64 + w * 8 + l];

    for (int tile = blockIdx.x; tile < N_TILES; tile += G_GRID) {
        const int q0 = tile * 64;

#pragma unroll
        for (int i = 0; i < 8; i++) {
            const int p = __shfl_sync(0xffffffffu, pv, i);
            const int q = w * 8 + i;             // local query 0..63
            const unsigned int dst =
                smem_base + (unsigned int)((q * 32 + (l ^ (q & 31))) * 8);
            const char* src = scr + (size_t)max(p, 0) * 256 + l * 8;
            const int sz = (p >= 0) ? 8 : 0;     // 0 -> 8B zero-fill
            asm volatile(
                "cp.async.ca.shared.global.L2::cache_hint [%0], [%1], 8, %2, %3;"
                :: "r"(dst), "l"(src), "r"(sz), "l"(pol) : "memory");
        }
        asm volatile("cp.async.commit_group;" ::: "memory");

        // Prefetch next tile's indices while the cp.asyncs drain.
        const int ntile = tile + G_GRID;
        int pv_next = 0;
        if (ntile < N_TILES && l < 8)
            pv_next = g_idx[ntile * 64 + w * 8 + l];

        asm volatile("cp.async.wait_group 0;" ::: "memory");
        __syncthreads();

#pragma unroll
        for (int j = 0; j < 4; j++) {
            const int u = w * 4 + j;             // 8B unit = channels 4u..4u+3
#pragma unroll
            for (int k = 0; k < 2; k++) {
                const int q = 32 * k + l;
                uint2 d = sm8[q * 32 + (u ^ l)]; // (q & 31) == l
                float2 f0 = __half22float2(*(const half2*)&d.x);
                float2 f1 = __half22float2(*(const half2*)&d.y);
                const size_t gq = (size_t)q0 + q;
                __stcs(&out[(size_t)(4 * u + 0) * NQ + gq], f0.x);
                __stcs(&out[(size_t)(4 * u + 1) * NQ + gq], f0.y);
                __stcs(&out[(size_t)(4 * u + 2) * NQ + gq], f1.x);
                __stcs(&out[(size_t)(4 * u + 3) * NQ + gq], f1.y);
            }
        }
        __syncthreads();                         // smem reuse guard
        pv = pv_next;
    }
}

// ---------------------------------------------------------------------------
extern "C" void kernel_launch(void* const* d_in, const int* in_sizes, int n_in,
                              void* d_out, int out_size) {
    const float* img   = (const float*)d_in[0];   // (6,128,64,176) f32
    const float* pts   = (const float*)d_in[1];   // (6,640000,2)  f32
    const void*  valid = d_in[2];                 // (6,640000) bool-ish
    float*       out   = (float*)d_out;           // (128,200,200,16) f32

    prologue_kernel<<<P_BLOCKS, 256>>>(img, pts, valid);
    gather_kernel<<<G_GRID, 256>>>(out);
}

// round 14
// speedup vs baseline: 1.0789x; 1.0789x over previous
#include <cuda_runtime.h>
#include <cuda_fp16.h>
#include <cstdint>
#include <cstddef>

#define N_CAM 6
#define C_CH  128
#define H_IMG 64
#define W_IMG 176
#define HW    (H_IMG * W_IMG)     // 11264
#define NQ    640000              // 200*200*16

// 64-channel x 32-hw transpose tiles: (HW/32) * (C/64) * N_CAM
#define TPC      ((HW / 32) * (C_CH / 64))           // 704 per cam
#define T_BLOCKS (TPC * N_CAM)                       // 4224
#define I_BLOCKS (NQ / 1024)                         // 625 (4 q/thread)
#define P_BLOCKS (T_BLOCKS + I_BLOCKS)               // 4849
#define I_SPAN   (7 * I_BLOCKS)                      // 4375 (bid%7==6 -> index)

// Scratch: img_feats transposed to (cam, h, w, c), fp16 (rn; measured
// whole-output rel_err 2.1e-4 << 1e-3). 17.3 MB static __device__.
__device__ __half g_scratch_h[(size_t)N_CAM * HW * C_CH];
// Per-query packed spatial index into scratch (row index), -1 invalid.
__device__ int g_idx[NQ];

// ---- cache-hinted accessors (createpolicy + L2::cache_hint) ----------------
__device__ __forceinline__ unsigned long long policy_evict_last() {
    unsigned long long p;
    asm("createpolicy.fractional.L2::evict_last.b64 %0, 1.0;" : "=l"(p));
    return p;
}
__device__ __forceinline__ void stg_el_u32(unsigned int* ptr, unsigned int v,
                                           unsigned long long pol) {
    asm volatile("st.global.L2::cache_hint.b32 [%0], %1, %2;"
                 :: "l"(ptr), "r"(v), "l"(pol));
}

// ---------------------------------------------------------------------------
// Fused prologue (R12, proven ~14.8us), role-interleaved (every 7th block ->
// index role).
// Role A: 64c x 32hw transpose tile, f32->fp16, half2-packed 128B store
//   wavefronts; scratch writes pinned in L2 (evict_last).
// Role B: index precompute, 4 queries/thread (uint/uint4 valid loads, 4
//   independent cam-selects + pts loads, one int4 g_idx store).
// Valid dtype detected per block: 1-byte bool has ~30% nonzero bytes at
// offsets ≡ 1 (mod 4); int32/f32 encodings of 0/1 have 0x00 there.
// 1024 samples -> P(false negative) ~ 0.7^1024.
// ---------------------------------------------------------------------------
__global__ __launch_bounds__(256) void prologue_kernel(
    const float* __restrict__ img,
    const float* __restrict__ pts,
    const void*  __restrict__ valid)
{
    const int tid = threadIdx.x;
    const int bid = blockIdx.x;
    const bool is_index = (bid < I_SPAN) && (bid % 7 == 6);

    if (!is_index) {
        // ---- transpose role: 64 channels x 32 hw positions ----
        const int t_id = (bid < I_SPAN) ? (bid - (bid + 1) / 7)
                                        : (bid - I_BLOCKS);
        __shared__ float tile[64][33];
        int b = t_id;
        const int cam = b / TPC;
        b -= cam * TPC;
        const int cb  = b / (HW / 32);               // 0..1
        const int hwb = b - cb * (HW / 32);
        const int hw0 = hwb * 32;
        const int c0  = cb * 64;
        const int tx = tid & 31, ty = tid >> 5;      // 32 x 8

        const unsigned long long pol = policy_evict_last();
        const float* src = img + (size_t)cam * C_CH * HW;
        __half*      dst = g_scratch_h + (size_t)cam * HW * C_CH;

#pragma unroll
        for (int k = 0; k < 8; k++) {
            int c = ty + k * 8;                      // 0..63 within tile
            tile[c][tx] = __ldcs(&src[(size_t)(c0 + c) * HW + hw0 + tx]);
        }
        __syncthreads();
#pragma unroll
        for (int i = 0; i < 4; i++) {
            const int r = ty * 4 + i;                // hw row 0..31
            __half2 h = __floats2half2_rn(tile[2 * tx][r], tile[2 * tx + 1][r]);
            unsigned int* p = (unsigned int*)
                (dst + (size_t)(hw0 + r) * C_CH + c0) + tx;
            stg_el_u32(p, *(unsigned int*)&h, pol);
        }
    } else {
        // ---- index role: 4 queries per thread ----
        const int q4 = (bid / 7) * 1024 + tid * 4;
        const unsigned char* vb = (const unsigned char*)valid;

        int found = 0;
#pragma unroll
        for (int j = 0; j < 4; j++)
            if (vb[1 + 4 * (tid * 4 + j)] != 0) found = 1;
        const int isByte = __syncthreads_or(found);

        unsigned int vmask[N_CAM];
        if (isByte) {
#pragma unroll
            for (int cc = 0; cc < N_CAM; cc++)
                vmask[cc] = *(const unsigned int*)(vb + (size_t)cc * NQ + q4);
        } else {
            const uint4* vw4 = (const uint4*)valid;
#pragma unroll
            for (int cc = 0; cc < N_CAM; cc++) {
                uint4 v = __ldg(&vw4[((size_t)cc * NQ + q4) >> 2]);
                vmask[cc] = (v.x ? 1u : 0u) | (v.y ? 0x100u : 0u) |
                            (v.z ? 0x10000u : 0u) | (v.w ? 0x1000000u : 0u);
            }
        }

        int4 pout;
        int* po = &pout.x;
#pragma unroll
        for (int j = 0; j < 4; j++) {
            int cam = -1;
#pragma unroll
            for (int cc = 0; cc < N_CAM; cc++)
                if ((vmask[cc] >> (8 * j)) & 0xffu) cam = cc;
            int p = -1;
            if (cam >= 0) {
                float2 sp = __ldg(&((const float2*)pts)[(size_t)cam * NQ + q4 + j]);
                int x = min(max(__float2int_rn(sp.x), 0), W_IMG - 1);
                int y = min(max(__float2int_rn(sp.y), 0), H_IMG - 1);
                p = cam * HW + y * W_IMG + x;
            }
            po[j] = p;
        }
        *(int4*)(g_idx + q4) = pout;
    }
}

// ---------------------------------------------------------------------------
// Gather (non-persistent, R12 structure; R13 proved cross-block overlap IS
// the pipeline): tile = 128 queries x 128 fp16 channels, 32KB smem, per-warp
// cp.async MLP=16 (MLP is the validated lever: R8/R9). 7 blocks/SM.
// Swizzled 8B layout: slot(q, u) = q*32 + (u ^ (q & 31)).
// Phase A: cp.async.ca 8B + L2 evict-hint; invalid queries zero-fill (size 0);
//   idx preloaded by 16 lanes (64B coalesced) + shuffle.
// Phase B: LDS.64 -> half2->float2 -> coalesced 128B STG.32 streams (__stcs
//   evict-first: the 328MB output stream must not evict the L2 scratch).
// ---------------------------------------------------------------------------
__global__ __launch_bounds__(256) void gather_kernel(float* __restrict__ out)
{
    __shared__ uint2 sm8[128 * 32];     // 32 KB
    const int tid = threadIdx.x;
    const int w = tid >> 5, l = tid & 31;
    const int q0 = blockIdx.x * 128;

    const unsigned long long pol = policy_evict_last();
    const char* scr = (const char*)g_scratch_h;

    int pv = 0;
    if (l < 16) pv = g_idx[q0 + w * 16 + l];

    const unsigned int smem_base =
        (unsigned int)__cvta_generic_to_shared(sm8);

#pragma unroll
    for (int i = 0; i < 16; i++) {
        const int p = __shfl_sync(0xffffffffu, pv, i);
        const int q = w * 16 + i;                // local query 0..127
        const unsigned int dst =
            smem_base + (unsigned int)((q * 32 + (l ^ (q & 31))) * 8);
        const char* src = scr + (size_t)max(p, 0) * 256 + l * 8;
        const int sz = (p >= 0) ? 8 : 0;         // 0 -> 8B zero-fill
        asm volatile(
            "cp.async.ca.shared.global.L2::cache_hint [%0], [%1], 8, %2, %3;"
            :: "r"(dst), "l"(src), "r"(sz), "l"(pol) : "memory");
    }
    asm volatile("cp.async.commit_group;" ::: "memory");
    asm volatile("cp.async.wait_group 0;" ::: "memory");
    __syncthreads();

#pragma unroll
    for (int j = 0; j < 4; j++) {
        const int u = w * 4 + j;                 // 8B unit = channels 4u..4u+3
#pragma unroll
        for (int k = 0; k < 4; k++) {
            const int q = 32 * k + l;
            uint2 d = sm8[q * 32 + (u ^ l)];     // (q & 31) == l
            float2 f0 = __half22float2(*(const half2*)&d.x);
            float2 f1 = __half22float2(*(const half2*)&d.y);
            const size_t gq = (size_t)q0 + q;
            __stcs(&out[(size_t)(4 * u + 0) * NQ + gq], f0.x);
            __stcs(&out[(size_t)(4 * u + 1) * NQ + gq], f0.y);
            __stcs(&out[(size_t)(4 * u + 2) * NQ + gq], f1.x);
            __stcs(&out[(size_t)(4 * u + 3) * NQ + gq], f1.y);
        }
    }
}

// ---------------------------------------------------------------------------
extern "C" void kernel_launch(void* const* d_in, const int* in_sizes, int n_in,
                              void* d_out, int out_size) {
    const float* img   = (const float*)d_in[0];   // (6,128,64,176) f32
    const float* pts   = (const float*)d_in[1];   // (6,640000,2)  f32
    const void*  valid = d_in[2];                 // (6,640000) bool-ish
    float*       out   = (float*)d_out;           // (128,200,200,16) f32

    prologue_kernel<<<P_BLOCKS, 256>>>(img, pts, valid);
    gather_kernel<<<NQ / 128, 256>>>(out);
}

// round 15
// speedup vs baseline: 1.0837x; 1.0045x over previous
#include <cuda_runtime.h>
#include <cuda_fp16.h>
#include <cstdint>
#include <cstddef>

#define N_CAM 6
#define C_CH  128
#define H_IMG 64
#define W_IMG 176
#define HW    (H_IMG * W_IMG)     // 11264
#define NQ    640000              // 200*200*16

// 64-channel x 32-hw transpose tiles: (HW/32) * (C/64) * N_CAM
#define TPC      ((HW / 32) * (C_CH / 64))           // 704 per cam
#define T_BLOCKS (TPC * N_CAM)                       // 4224
#define I_BLOCKS (NQ / 1024)                         // 625 (4 q/thread)
#define P_BLOCKS (T_BLOCKS + I_BLOCKS)               // 4849
#define I_SPAN   (7 * I_BLOCKS)                      // 4375 (bid%7==6 -> index)

// Scratch: img_feats transposed to (cam, h, w, c), fp16 (rn; measured
// whole-output rel_err 2.1e-4 << 1e-3). 17.3 MB static __device__.
__device__ __half g_scratch_h[(size_t)N_CAM * HW * C_CH];
// Per-query packed spatial index into scratch (row index), -1 invalid.
__device__ int g_idx[NQ];

// ---- cache-hinted accessors (createpolicy + L2::cache_hint) ----------------
__device__ __forceinline__ unsigned long long policy_evict_last() {
    unsigned long long p;
    asm("createpolicy.fractional.L2::evict_last.b64 %0, 1.0;" : "=l"(p));
    return p;
}
__device__ __forceinline__ void stg_el_u32(unsigned int* ptr, unsigned int v,
                                           unsigned long long pol) {
    asm volatile("st.global.L2::cache_hint.b32 [%0], %1, %2;"
                 :: "l"(ptr), "r"(v), "l"(pol));
}

// ---------------------------------------------------------------------------
// Fused prologue (R12, proven), role-interleaved (every 7th block -> index).
// Role A: 64c x 32hw transpose tile, f32->fp16, half2-packed 128B store
//   wavefronts; scratch writes pinned in L2 (evict_last).
// Role B: index precompute, 4 queries/thread (uint/uint4 valid loads, 4
//   independent cam-selects + pts loads, one int4 g_idx store).
// Valid dtype detected per block: 1-byte bool has ~30% nonzero bytes at
// offsets ≡ 1 (mod 4); int32/f32 encodings of 0/1 have 0x00 there.
// 1024 samples -> P(false negative) ~ 0.7^1024.
// Each block triggers PDL completion after its last store so the gather's
// front edge overlaps this kernel's tail drain.
// ---------------------------------------------------------------------------
__global__ __launch_bounds__(256) void prologue_kernel(
    const float* __restrict__ img,
    const float* __restrict__ pts,
    const void*  __restrict__ valid)
{
    const int tid = threadIdx.x;
    const int bid = blockIdx.x;
    const bool is_index = (bid < I_SPAN) && (bid % 7 == 6);

    if (!is_index) {
        // ---- transpose role: 64 channels x 32 hw positions ----
        const int t_id = (bid < I_SPAN) ? (bid - (bid + 1) / 7)
                                        : (bid - I_BLOCKS);
        __shared__ float tile[64][33];
        int b = t_id;
        const int cam = b / TPC;
        b -= cam * TPC;
        const int cb  = b / (HW / 32);               // 0..1
        const int hwb = b - cb * (HW / 32);
        const int hw0 = hwb * 32;
        const int c0  = cb * 64;
        const int tx = tid & 31, ty = tid >> 5;      // 32 x 8

        const unsigned long long pol = policy_evict_last();
        const float* src = img + (size_t)cam * C_CH * HW;
        __half*      dst = g_scratch_h + (size_t)cam * HW * C_CH;

#pragma unroll
        for (int k = 0; k < 8; k++) {
            int c = ty + k * 8;                      // 0..63 within tile
            tile[c][tx] = __ldcs(&src[(size_t)(c0 + c) * HW + hw0 + tx]);
        }
        __syncthreads();
#pragma unroll
        for (int i = 0; i < 4; i++) {
            const int r = ty * 4 + i;                // hw row 0..31
            __half2 h = __floats2half2_rn(tile[2 * tx][r], tile[2 * tx + 1][r]);
            unsigned int* p = (unsigned int*)
                (dst + (size_t)(hw0 + r) * C_CH + c0) + tx;
            stg_el_u32(p, *(unsigned int*)&h, pol);
        }
    } else {
        // ---- index role: 4 queries per thread ----
        const int q4 = (bid / 7) * 1024 + tid * 4;
        const unsigned char* vb = (const unsigned char*)valid;

        int found = 0;
#pragma unroll
        for (int j = 0; j < 4; j++)
            if (vb[1 + 4 * (tid * 4 + j)] != 0) found = 1;
        const int isByte = __syncthreads_or(found);

        unsigned int vmask[N_CAM];
        if (isByte) {
#pragma unroll
            for (int cc = 0; cc < N_CAM; cc++)
                vmask[cc] = *(const unsigned int*)(vb + (size_t)cc * NQ + q4);
        } else {
            const uint4* vw4 = (const uint4*)valid;
#pragma unroll
            for (int cc = 0; cc < N_CAM; cc++) {
                uint4 v = __ldg(&vw4[((size_t)cc * NQ + q4) >> 2]);
                vmask[cc] = (v.x ? 1u : 0u) | (v.y ? 0x100u : 0u) |
                            (v.z ? 0x10000u : 0u) | (v.w ? 0x1000000u : 0u);
            }
        }

        int4 pout;
        int* po = &pout.x;
#pragma unroll
        for (int j = 0; j < 4; j++) {
            int cam = -1;
#pragma unroll
            for (int cc = 0; cc < N_CAM; cc++)
                if ((vmask[cc] >> (8 * j)) & 0xffu) cam = cc;
            int p = -1;
            if (cam >= 0) {
                float2 sp = __ldg(&((const float2*)pts)[(size_t)cam * NQ + q4 + j]);
                int x = min(max(__float2int_rn(sp.x), 0), W_IMG - 1);
                int y = min(max(__float2int_rn(sp.y), 0), H_IMG - 1);
                p = cam * HW + y * W_IMG + x;
            }
            po[j] = p;
        }
        *(int4*)(g_idx + q4) = pout;
    }

    // PDL: all stores for this block are issued; let dependents launch.
    cudaTriggerProgrammaticLaunchCompletion();
}

// ---------------------------------------------------------------------------
// Gather (R14, best measured 55.2us): 128 queries x 128 fp16 channels, 32KB
// smem, per-warp cp.async MLP=16 (the validated lever). Non-persistent:
// cross-block overlap is the pipeline (R13 lesson).
// PDL: setup (policy, smem addresses) happens pre-sync; the grid-dependency
// wait sits immediately before the first g_idx load.
// Swizzled 8B layout: slot(q, u) = q*32 + (u ^ (q & 31)).
// Phase A: cp.async.ca 8B + L2 evict-hint; invalid queries zero-fill (size 0);
//   idx preloaded by 16 lanes (64B coalesced) + shuffle.
// Phase B: LDS.64 -> half2->float2 -> coalesced 128B STG.32 streams (__stcs
//   evict-first: the 328MB output stream must not evict the L2 scratch).
// ---------------------------------------------------------------------------
__global__ __launch_bounds__(256) void gather_kernel(float* __restrict__ out)
{
    __shared__ uint2 sm8[128 * 32];     // 32 KB
    const int tid = threadIdx.x;
    const int w = tid >> 5, l = tid & 31;
    const int q0 = blockIdx.x * 128;

    const unsigned long long pol = policy_evict_last();
    const char* scr = (const char*)g_scratch_h;
    const unsigned int smem_base =
        (unsigned int)__cvta_generic_to_shared(sm8);

    // Wait for the prologue's stores to be visible, then go.
    cudaGridDependencySynchronize();

    int pv = 0;
    if (l < 16) pv = g_idx[q0 + w * 16 + l];

#pragma unroll
    for (int i = 0; i < 16; i++) {
        const int p = __shfl_sync(0xffffffffu, pv, i);
        const int q = w * 16 + i;                // local query 0..127
        const unsigned int dst =
            smem_base + (unsigned int)((q * 32 + (l ^ (q & 31))) * 8);
        const char* src = scr + (size_t)max(p, 0) * 256 + l * 8;
        const int sz = (p >= 0) ? 8 : 0;         // 0 -> 8B zero-fill
        asm volatile(
            "cp.async.ca.shared.global.L2::cache_hint [%0], [%1], 8, %2, %3;"
            :: "r"(dst), "l"(src), "r"(sz), "l"(pol) : "memory");
    }
    asm volatile("cp.async.commit_group;" ::: "memory");
    asm volatile("cp.async.wait_group 0;" ::: "memory");
    __syncthreads();

#pragma unroll
    for (int j = 0; j < 4; j++) {
        const int u = w * 4 + j;                 // 8B unit = channels 4u..4u+3
#pragma unroll
        for (int k = 0; k < 4; k++) {
            const int q = 32 * k + l;
            uint2 d = sm8[q * 32 + (u ^ l)];     // (q & 31) == l
            float2 f0 = __half22float2(*(const half2*)&d.x);
            float2 f1 = __half22float2(*(const half2*)&d.y);
            const size_t gq = (size_t)q0 + q;
            __stcs(&out[(size_t)(4 * u + 0) * NQ + gq], f0.x);
            __stcs(&out[(size_t)(4 * u + 1) * NQ + gq], f0.y);
            __stcs(&out[(size_t)(4 * u + 2) * NQ + gq], f1.x);
            __stcs(&out[(size_t)(4 * u + 3) * NQ + gq], f1.y);
        }
    }
}

// ---------------------------------------------------------------------------
extern "C" void kernel_launch(void* const* d_in, const int* in_sizes, int n_in,
                              void* d_out, int out_size) {
    const float* img   = (const float*)d_in[0];   // (6,128,64,176) f32
    const float* pts   = (const float*)d_in[1];   // (6,640000,2)  f32
    const void*  valid = d_in[2];                 // (6,640000) bool-ish
    float*       out   = (float*)d_out;           // (128,200,200,16) f32

    prologue_kernel<<<P_BLOCKS, 256>>>(img, pts, valid);

    // Gather with programmatic dependent launch: overlaps its launch/setup
    // with the prologue's tail drain; data dependency enforced by the
    // device-side grid sync.
    cudaLaunchConfig_t cfg = {};
    cfg.gridDim  = dim3(NQ / 128, 1, 1);
    cfg.blockDim = dim3(256, 1, 1);
    cfg.dynamicSmemBytes = 0;
    cfg.stream = 0;
    cudaLaunchAttribute attr[1];
    attr[0].id = cudaLaunchAttributeProgrammaticStreamSerialization;
    attr[0].val.programmaticStreamSerializationAllowed = 1;
    cfg.attrs = attr;
    cfg.numAttrs = 1;
    cudaLaunchKernelEx(&cfg, gather_kernel, out);
}

// round 16
// speedup vs baseline: 1.0852x; 1.0013x over previous
#include <cuda_runtime.h>
#include <cuda_fp16.h>
#include <cstdint>
#include <cstddef>

#define N_CAM 6
#define C_CH  128
#define H_IMG 64
#define W_IMG 176
#define HW    (H_IMG * W_IMG)     // 11264
#define NQ    640000              // 200*200*16

// 64-channel x 64-hw transpose tiles: (HW/64) * (C/64) * N_CAM
#define TPC      ((HW / 64) * (C_CH / 64))           // 352 per cam
#define T_BLOCKS (TPC * N_CAM)                       // 2112
#define I_BLOCKS (NQ / 1024)                         // 625 (4 q/thread)
#define P_BLOCKS (T_BLOCKS + I_BLOCKS)               // 2737
#define I_SPAN   (4 * I_BLOCKS)                      // 2500 (bid%4==3 -> index)

// Scratch: img_feats transposed to (cam, h, w, c), fp16 (rn; measured
// whole-output rel_err 2.1e-4 << 1e-3). 17.3 MB static __device__.
__device__ __half g_scratch_h[(size_t)N_CAM * HW * C_CH];
// Per-query packed spatial index into scratch (row index), -1 invalid.
__device__ int g_idx[NQ];

// ---- cache-hinted accessors (createpolicy + L2::cache_hint) ----------------
__device__ __forceinline__ unsigned long long policy_evict_last() {
    unsigned long long p;
    asm("createpolicy.fractional.L2::evict_last.b64 %0, 1.0;" : "=l"(p));
    return p;
}
__device__ __forceinline__ void stg_el_u32(unsigned int* ptr, unsigned int v,
                                           unsigned long long pol) {
    asm volatile("st.global.L2::cache_hint.b32 [%0], %1, %2;"
                 :: "l"(ptr), "r"(v), "l"(pol));
}
__device__ __forceinline__ float2 ldcs_f2(const float2* p) {
    float2 v;
    asm volatile("ld.global.cs.v2.f32 {%0,%1}, [%2];"
                 : "=f"(v.x), "=f"(v.y) : "l"(p));
    return v;
}

// ---------------------------------------------------------------------------
// Fused prologue, role-interleaved (every 4th block -> index role).
// Role A: 64c x 64hw transpose tile with float2 streaming loads (half the
//   load instructions and half the blocks of the R12 form), f32->fp16,
//   half2-packed 128B store wavefronts; scratch writes pinned in L2
//   (evict_last) so the gather's re-reads stay resident.
// Role B: index precompute, 4 queries/thread (uint/uint4 valid loads, 4
//   independent cam-selects + pts loads, one int4 g_idx store).
// Valid dtype detected per block: 1-byte bool has ~30% nonzero bytes at
// offsets ≡ 1 (mod 4); int32/f32 encodings of 0/1 have 0x00 there.
// 1024 samples -> P(false negative) ~ 0.7^1024.
// Each block triggers PDL completion after its last store.
// ---------------------------------------------------------------------------
__global__ __launch_bounds__(256) void prologue_kernel(
    const float* __restrict__ img,
    const float* __restrict__ pts,
    const void*  __restrict__ valid)
{
    const int tid = threadIdx.x;
    const int bid = blockIdx.x;
    const bool is_index = (bid < I_SPAN) && ((bid & 3) == 3);

    if (!is_index) {
        // ---- transpose role: 64 channels x 64 hw positions ----
        const int t_id = (bid < I_SPAN) ? (bid - ((bid + 1) >> 2))
                                        : (bid - I_BLOCKS);
        __shared__ float tile[64][65];               // pad 65: STS.64 clean
        int b = t_id;
        const int cam = b / TPC;
        b -= cam * TPC;
        const int cb  = b / (HW / 64);               // 0..1
        const int hwb = b - cb * (HW / 64);
        const int hw0 = hwb * 64;
        const int c0  = cb * 64;
        const int tx = tid & 31, ty = tid >> 5;      // 32 x 8

        const unsigned long long pol = policy_evict_last();
        const float* src = img + (size_t)cam * C_CH * HW;
        __half*      dst = g_scratch_h + (size_t)cam * HW * C_CH;

#pragma unroll
        for (int k = 0; k < 8; k++) {
            const int c = ty + k * 8;                // 0..63 within tile
            float2 v = ldcs_f2((const float2*)
                (src + (size_t)(c0 + c) * HW + hw0) + tx);
            tile[c][2 * tx]     = v.x;
            tile[c][2 * tx + 1] = v.y;
        }
        __syncthreads();
        // Store: warp handles 8 hw rows; lane tx packs channels (2tx, 2tx+1)
        // into one half2 -> 32 x 4B = 128B contiguous per row.
#pragma unroll
        for (int i = 0; i < 8; i++) {
            const int r = ty * 8 + i;                // hw row 0..63
            __half2 h = __floats2half2_rn(tile[2 * tx][r], tile[2 * tx + 1][r]);
            unsigned int* p = (unsigned int*)
                (dst + (size_t)(hw0 + r) * C_CH + c0) + tx;
            stg_el_u32(p, *(unsigned int*)&h, pol);
        }
    } else {
        // ---- index role: 4 queries per thread ----
        const int q4 = (bid >> 2) * 1024 + tid * 4;
        const unsigned char* vb = (const unsigned char*)valid;

        int found = 0;
#pragma unroll
        for (int j = 0; j < 4; j++)
            if (vb[1 + 4 * (tid * 4 + j)] != 0) found = 1;
        const int isByte = __syncthreads_or(found);

        unsigned int vmask[N_CAM];
        if (isByte) {
#pragma unroll
            for (int cc = 0; cc < N_CAM; cc++)
                vmask[cc] = *(const unsigned int*)(vb + (size_t)cc * NQ + q4);
        } else {
            const uint4* vw4 = (const uint4*)valid;
#pragma unroll
            for (int cc = 0; cc < N_CAM; cc++) {
                uint4 v = __ldg(&vw4[((size_t)cc * NQ + q4) >> 2]);
                vmask[cc] = (v.x ? 1u : 0u) | (v.y ? 0x100u : 0u) |
                            (v.z ? 0x10000u : 0u) | (v.w ? 0x1000000u : 0u);
            }
        }

        int4 pout;
        int* po = &pout.x;
#pragma unroll
        for (int j = 0; j < 4; j++) {
            int cam = -1;
#pragma unroll
            for (int cc = 0; cc < N_CAM; cc++)
                if ((vmask[cc] >> (8 * j)) & 0xffu) cam = cc;
            int p = -1;
            if (cam >= 0) {
                float2 sp = __ldg(&((const float2*)pts)[(size_t)cam * NQ + q4 + j]);
                int x = min(max(__float2int_rn(sp.x), 0), W_IMG - 1);
                int y = min(max(__float2int_rn(sp.y), 0), H_IMG - 1);
                p = cam * HW + y * W_IMG + x;
            }
            po[j] = p;
        }
        *(int4*)(g_idx + q4) = pout;
    }

    cudaTriggerProgrammaticLaunchCompletion();
}

// ---------------------------------------------------------------------------
// Gather (R14 form, proven 55.2us ~= DRAM write-drain ceiling; UNCHANGED):
// 128 queries x 128 fp16 channels, 32KB smem, per-warp cp.async MLP=16.
// Non-persistent: cross-block overlap is the pipeline (R13 lesson).
// Swizzled 8B layout: slot(q, u) = q*32 + (u ^ (q & 31)).
// Phase A: cp.async.ca 8B + L2 evict-hint; invalid queries zero-fill (size 0);
//   idx preloaded by 16 lanes (64B coalesced) + shuffle.
// Phase B: LDS.64 -> half2->float2 -> coalesced 128B STG.32 streams (__stcs
//   evict-first: the 328MB output stream must not evict the L2 scratch).
// ---------------------------------------------------------------------------
__global__ __launch_bounds__(256) void gather_kernel(float* __restrict__ out)
{
    __shared__ uint2 sm8[128 * 32];     // 32 KB
    const int tid = threadIdx.x;
    const int w = tid >> 5, l = tid & 31;
    const int q0 = blockIdx.x * 128;

    const unsigned long long pol = policy_evict_last();
    const char* scr = (const char*)g_scratch_h;
    const unsigned int smem_base =
        (unsigned int)__cvta_generic_to_shared(sm8);

    cudaGridDependencySynchronize();

    int pv = 0;
    if (l < 16) pv = g_idx[q0 + w * 16 + l];

#pragma unroll
    for (int i = 0; i < 16; i++) {
        const int p = __shfl_sync(0xffffffffu, pv, i);
        const int q = w * 16 + i;                // local query 0..127
        const unsigned int dst =
            smem_base + (unsigned int)((q * 32 + (l ^ (q & 31))) * 8);
        const char* src = scr + (size_t)max(p, 0) * 256 + l * 8;
        const int sz = (p >= 0) ? 8 : 0;         // 0 -> 8B zero-fill
        asm volatile(
            "cp.async.ca.shared.global.L2::cache_hint [%0], [%1], 8, %2, %3;"
            :: "r"(dst), "l"(src), "r"(sz), "l"(pol) : "memory");
    }
    asm volatile("cp.async.commit_group;" ::: "memory");
    asm volatile("cp.async.wait_group 0;" ::: "memory");
    __syncthreads();

#pragma unroll
    for (int j = 0; j < 4; j++) {
        const int u = w * 4 + j;                 // 8B unit = channels 4u..4u+3
#pragma unroll
        for (int k = 0; k < 4; k++) {
            const int q = 32 * k + l;
            uint2 d = sm8[q * 32 + (u ^ l)];     // (q & 31) == l
            float2 f0 = __half22float2(*(const half2*)&d.x);
            float2 f1 = __half22float2(*(const half2*)&d.y);
            const size_t gq = (size_t)q0 + q;
            __stcs(&out[(size_t)(4 * u + 0) * NQ + gq], f0.x);
            __stcs(&out[(size_t)(4 * u + 1) * NQ + gq], f0.y);
            __stcs(&out[(size_t)(4 * u + 2) * NQ + gq], f1.x);
            __stcs(&out[(size_t)(4 * u + 3) * NQ + gq], f1.y);
        }
    }
}

// ---------------------------------------------------------------------------
extern "C" void kernel_launch(void* const* d_in, const int* in_sizes, int n_in,
                              void* d_out, int out_size) {
    const float* img   = (const float*)d_in[0];   // (6,128,64,176) f32
    const float* pts   = (const float*)d_in[1];   // (6,640000,2)  f32
    const void*  valid = d_in[2];                 // (6,640000) bool-ish
    float*       out   = (float*)d_out;           // (128,200,200,16) f32

    prologue_kernel<<<P_BLOCKS, 256>>>(img, pts, valid);

    cudaLaunchConfig_t cfg = {};
    cfg.gridDim  = dim3(NQ / 128, 1, 1);
    cfg.blockDim = dim3(256, 1, 1);
    cfg.dynamicSmemBytes = 0;
    cfg.stream = 0;
    cudaLaunchAttribute attr[1];
    attr[0].id = cudaLaunchAttributeProgrammaticStreamSerialization;
    attr[0].val.programmaticStreamSerializationAllowed = 1;
    cfg.attrs = attr;
    cfg.numAttrs = 1;
    cudaLaunchKernelEx(&cfg, gather_kernel, out);
}